// round 14
// baseline (speedup 1.0000x reference)
#include <cuda_runtime.h>

#define NSC     4096
#define NT      14
#define PAD(f)  ((f) + ((f) >> 3))
#define RSQ2    0.70710678118654752f
#define BMAX    2048
#define NCHUNK  8

// odd-subcarrier real parts, [cta = b*2+s][2048]
__device__ float g_odd[(size_t)BMAX * 2 * 2048];

__constant__ float c_w[NT] = {0.f, 0.f, 0.f, 1.f/9, 2.f/9, 3.f/9, 4.f/9, 5.f/9,
                              6.f/9, 7.f/9, 8.f/9, 1.f, 1.f, 1.f};

__device__ __forceinline__ float2 cadd(float2 a, float2 b) { return make_float2(a.x + b.x, a.y + b.y); }
__device__ __forceinline__ float2 csub(float2 a, float2 b) { return make_float2(a.x - b.x, a.y - b.y); }
__device__ __forceinline__ float2 cmul(float2 a, float2 b) {
    return make_float2(a.x * b.x - a.y * b.y, a.x * b.y + a.y * b.x);
}

__device__ __forceinline__ void fwd8(float2* __restrict__ A, const float2* __restrict__ Tb,
                                     int q, int h, int str) {
    int j    = q & (h - 1);
    int base = ((q - j) << 3) + j;
    float2 t0 = A[PAD(base)],         t1 = A[PAD(base + h)];
    float2 t2 = A[PAD(base + 2 * h)], t3 = A[PAD(base + 3 * h)];
    float2 t4 = A[PAD(base + 4 * h)], t5 = A[PAD(base + 5 * h)];
    float2 t6 = A[PAD(base + 6 * h)], t7 = A[PAD(base + 7 * h)];

    float2 a0 = cadd(t0, t4), a1 = cadd(t1, t5), a2 = cadd(t2, t6), a3 = cadd(t3, t7);
    float2 b0 = csub(t0, t4), b1 = csub(t1, t5), b2 = csub(t2, t6), b3 = csub(t3, t7);
    float2 c0 = cadd(a0, a2), c1 = csub(a0, a2), c2 = cadd(a1, a3), c3 = csub(a1, a3);
    float2 X0 = cadd(c0, c2), X4 = csub(c0, c2);
    float2 X2 = make_float2(c1.x + c3.y, c1.y - c3.x);
    float2 X6 = make_float2(c1.x - c3.y, c1.y + c3.x);
    float2 d0 = b0;
    float2 d1 = make_float2(RSQ2 * (b1.x + b1.y), RSQ2 * (b1.y - b1.x));
    float2 d2 = make_float2(b2.y, -b2.x);
    float2 d3 = make_float2(RSQ2 * (b3.y - b3.x), RSQ2 * (-(b3.x + b3.y)));
    float2 e0 = cadd(d0, d2), ee1 = csub(d0, d2), e2 = cadd(d1, d3), e3 = csub(d1, d3);
    float2 X1 = cadd(e0, e2), X5 = csub(e0, e2);
    float2 X3 = make_float2(ee1.x + e3.y, ee1.y - e3.x);
    float2 X7 = make_float2(ee1.x - e3.y, ee1.y + e3.x);

    float2 w1 = Tb[j * str]; w1.y = -w1.y;
    float2 w2 = cmul(w1, w1);
    float2 w3 = cmul(w2, w1);
    float2 w4 = cmul(w2, w2);
    float2 w5 = cmul(w4, w1);
    float2 w6 = cmul(w4, w2);
    float2 w7 = cmul(w4, w3);
    A[PAD(base)]         = X0;
    A[PAD(base + h)]     = cmul(X1, w1);
    A[PAD(base + 2 * h)] = cmul(X2, w2);
    A[PAD(base + 3 * h)] = cmul(X3, w3);
    A[PAD(base + 4 * h)] = cmul(X4, w4);
    A[PAD(base + 5 * h)] = cmul(X5, w5);
    A[PAD(base + 6 * h)] = cmul(X6, w6);
    A[PAD(base + 7 * h)] = cmul(X7, w7);
}

template <bool LAST>
__device__ __forceinline__ void inv8(float2* __restrict__ A, float* __restrict__ R,
                                     const float2* __restrict__ Tb,
                                     int q, int h, int str) {
    int j    = q & (h - 1);
    int base = ((q - j) << 3) + j;
    float2 w1 = Tb[j * str];
    float2 w2 = cmul(w1, w1);
    float2 w3 = cmul(w2, w1);
    float2 w4 = cmul(w2, w2);
    float2 w5 = cmul(w4, w1);
    float2 w6 = cmul(w4, w2);
    float2 w7 = cmul(w4, w3);
    float2 t0 = A[PAD(base)];
    float2 t1 = cmul(A[PAD(base + h)],     w1);
    float2 t2 = cmul(A[PAD(base + 2 * h)], w2);
    float2 t3 = cmul(A[PAD(base + 3 * h)], w3);
    float2 t4 = cmul(A[PAD(base + 4 * h)], w4);
    float2 t5 = cmul(A[PAD(base + 5 * h)], w5);
    float2 t6 = cmul(A[PAD(base + 6 * h)], w6);
    float2 t7 = cmul(A[PAD(base + 7 * h)], w7);

    float2 a0 = cadd(t0, t4), a1 = cadd(t1, t5), a2 = cadd(t2, t6), a3 = cadd(t3, t7);
    float2 b0 = csub(t0, t4), b1 = csub(t1, t5), b2 = csub(t2, t6), b3 = csub(t3, t7);
    float2 c0 = cadd(a0, a2), c1 = csub(a0, a2), c2 = cadd(a1, a3), c3 = csub(a1, a3);
    float2 X0 = cadd(c0, c2), X4 = csub(c0, c2);
    float2 X2 = make_float2(c1.x - c3.y, c1.y + c3.x);
    float2 X6 = make_float2(c1.x + c3.y, c1.y - c3.x);
    float2 d0 = b0;
    float2 d1 = make_float2(RSQ2 * (b1.x - b1.y), RSQ2 * (b1.y + b1.x));
    float2 d2 = make_float2(-b2.y, b2.x);
    float2 d3 = make_float2(RSQ2 * (-(b3.x + b3.y)), RSQ2 * (b3.x - b3.y));
    float2 e0 = cadd(d0, d2), ee1 = csub(d0, d2), e2 = cadd(d1, d3), e3 = csub(d1, d3);
    float2 X1 = cadd(e0, e2), X5 = csub(e0, e2);
    float2 X3 = make_float2(ee1.x - e3.y, ee1.y + e3.x);
    float2 X7 = make_float2(ee1.x + e3.y, ee1.y - e3.x);

    if (LAST) {
        R[base]         = X0.x;
        R[base + h]     = X1.x;
        R[base + 2 * h] = X2.x;
        R[base + 3 * h] = X3.x;
        R[base + 4 * h] = X4.x;
        R[base + 5 * h] = X5.x;
        R[base + 6 * h] = X6.x;
        R[base + 7 * h] = X7.x;
    } else {
        A[PAD(base)]         = X0;
        A[PAD(base + h)]     = X1;
        A[PAD(base + 2 * h)] = X2;
        A[PAD(base + 3 * h)] = X3;
        A[PAD(base + 4 * h)] = X4;
        A[PAD(base + 5 * h)] = X5;
        A[PAD(base + 6 * h)] = X6;
        A[PAD(base + 7 * h)] = X7;
    }
}

// ---------- K1: one 2048-pt fwd+twiddle+inv per CTA (cta index offset by cta0) ----------
__global__ __launch_bounds__(128, 8) void fft_kernel(const float* __restrict__ pr,
                                                     const float* __restrict__ pi,
                                                     long long n0, long long n1, int cta0)
{
    __shared__ float2 sh[256 + 2304];   // Tb | Y (padded 2048)
    float2* Tb = sh;
    float2* Y  = sh + 256;

    const int tid = threadIdx.x;
    const int cta = cta0 + blockIdx.x;              // cta = b*2 + s
    const long long base = (long long)cta * 2048;

    for (int m = tid; m < 256; m += 128) {
        float s, c;
        __sincosf((float)m * 3.0679615757712823e-3f, &s, &c);   // 2*pi/2048
        Tb[m] = make_float2(c, s);
    }
    for (int n = tid; n < 2048; n += 128) {
        long long i = base + n;
        float r = (i < n0) ? pr[i] : 0.0f;
        float q = (i < n1) ? pi[i] : 0.0f;
        Y[PAD(n)] = make_float2(r, q);
    }
    __syncthreads();

    fwd8(Y, Tb, tid, 256, 1);  fwd8(Y, Tb, tid + 128, 256, 1);  __syncthreads();
    fwd8(Y, Tb, tid, 32,  8);  fwd8(Y, Tb, tid + 128, 32,  8);  __syncthreads();
    fwd8(Y, Tb, tid, 4,   64); fwd8(Y, Tb, tid + 128, 4,   64); __syncthreads();

    #pragma unroll
    for (int k = 0; k < 4; k++) {
        int m = tid + k * 128;
        int revm = ((m & 7) << 6) | (m & 56) | (m >> 6);
        float sn, cs;
        __sincosf((float)revm * 1.5339807878856412e-3f, &sn, &cs);   // 2*pi/4096
        float2 w0 = make_float2(cs * (1.0f / 2048.0f), sn * (1.0f / 2048.0f));
        float2 wA = make_float2(RSQ2 * (w0.x - w0.y), RSQ2 * (w0.x + w0.y));
        float2 wB = make_float2(w0.y, -w0.x);
        float2 wC = make_float2(RSQ2 * (w0.x + w0.y), RSQ2 * (w0.y - w0.x));
        int p = 4 * m;
        float2 t0 = Y[PAD(p)],     t1 = Y[PAD(p + 1)];
        float2 t2 = Y[PAD(p + 2)], t3 = Y[PAD(p + 3)];
        float2 a = cadd(t0, t2), bb = csub(t0, t2);
        float2 c = cadd(t1, t3), d  = csub(t1, t3);
        float2 F0 = cadd(a, c);
        float2 F1 = make_float2(bb.x + d.y, bb.y - d.x);
        float2 F2 = csub(a, c);
        float2 F3 = make_float2(bb.x - d.y, bb.y + d.x);
        float2 G0 = cmul(F0, w0), G1 = cmul(F1, wA);
        float2 G2 = cmul(F2, wB), G3 = cmul(F3, wC);
        float2 ap = cadd(G0, G2), bp = csub(G0, G2);
        float2 cp = cadd(G1, G3), dp = csub(G1, G3);
        Y[PAD(p)]     = cadd(ap, cp);
        Y[PAD(p + 2)] = csub(ap, cp);
        Y[PAD(p + 1)] = make_float2(bp.x - dp.y, bp.y + dp.x);
        Y[PAD(p + 3)] = make_float2(bp.x + dp.y, bp.y - dp.x);
    }
    __syncthreads();

    inv8<false>(Y, (float*)0, Tb, tid, 4,  64); inv8<false>(Y, (float*)0, Tb, tid + 128, 4,  64); __syncthreads();
    inv8<false>(Y, (float*)0, Tb, tid, 32, 8);  inv8<false>(Y, (float*)0, Tb, tid + 128, 32, 8);  __syncthreads();
    float* R = g_odd + (size_t)cta * 2048;
    inv8<true>(Y, R, Tb, tid, 256, 1);  inv8<true>(Y, R, Tb, tid + 128, 256, 1);
}

// ---------- K2: broadcast/lerp for batches [b0, b0 + chunk) ----------
__global__ __launch_bounds__(256) void out_kernel(const float* __restrict__ pr,
                                                  float4* __restrict__ out,
                                                  long long n0, long long cap_f4,
                                                  int b0, int B)
{
    int idx = blockIdx.x * 256 + threadIdx.x;
    int b = b0 + (idx >> 10);
    int u = idx & 1023;
    if (b >= B) return;
    const long long base = (long long)b * 4096;

    float2 e0, e1;
    if (base + 4096 <= n0) {
        const float2* pr2 = (const float2*)pr;
        e0 = pr2[(base >> 1) + u];
        e1 = pr2[(base >> 1) + 1024 + u];
    } else {
        e0.x = (base + 2 * u < n0) ? pr[base + 2 * u] : 0.0f;
        e0.y = (base + 2 * u + 1 < n0) ? pr[base + 2 * u + 1] : 0.0f;
        e1.x = (base + 2048 + 2 * u < n0) ? pr[base + 2048 + 2 * u] : 0.0f;
        e1.y = (base + 2048 + 2 * u + 1 < n0) ? pr[base + 2048 + 2 * u + 1] : 0.0f;
    }
    const float2* o0p = (const float2*)(g_odd + (size_t)(2 * b) * 2048);
    const float2* o1p = (const float2*)(g_odd + (size_t)(2 * b + 1) * 2048);
    float2 o0 = o0p[u];
    float2 o1 = o1p[u];

    const long long obf4 = (long long)b * (NT * NSC / 4);
    if (obf4 + (long long)NT * (NSC / 4) <= cap_f4) {
        #pragma unroll
        for (int t = 0; t < NT; t++) {
            float w = c_w[t];
            float4 v;
            v.x = e0.x + (e1.x - e0.x) * w;
            v.y = o0.x + (o1.x - o0.x) * w;
            v.z = e0.y + (e1.y - e0.y) * w;
            v.w = o0.y + (o1.y - o0.y) * w;
            out[obf4 + (long long)t * (NSC / 4) + u] = v;
        }
    } else {
        #pragma unroll
        for (int t = 0; t < NT; t++) {
            float w = c_w[t];
            long long f4 = obf4 + (long long)t * (NSC / 4) + u;
            if (f4 < cap_f4) {
                float4 v;
                v.x = e0.x + (e1.x - e0.x) * w;
                v.y = o0.x + (o1.x - o0.x) * w;
                v.z = e0.y + (e1.y - e0.y) * w;
                v.w = o0.y + (o1.y - o0.y) * w;
                out[f4] = v;
            }
        }
    }
}

// ---------- streams/events, created pre-main so any internal allocations land
// ---------- in the harness's memory baseline (no allocs inside kernel_launch)
static cudaStream_t g_sA = 0, g_sB = 0;
static cudaEvent_t  g_evRoot = 0, g_evJoin = 0, g_evK1[NCHUNK];
static bool g_ok = []() {
    if (cudaStreamCreateWithFlags(&g_sA, cudaStreamNonBlocking) != cudaSuccess) return false;
    if (cudaStreamCreateWithFlags(&g_sB, cudaStreamNonBlocking) != cudaSuccess) return false;
    if (cudaEventCreateWithFlags(&g_evRoot, cudaEventDisableTiming) != cudaSuccess) return false;
    if (cudaEventCreateWithFlags(&g_evJoin, cudaEventDisableTiming) != cudaSuccess) return false;
    for (int i = 0; i < NCHUNK; i++)
        if (cudaEventCreateWithFlags(&g_evK1[i], cudaEventDisableTiming) != cudaSuccess) return false;
    return true;
}();

extern "C" void kernel_launch(void* const* d_in, const int* in_sizes, int n_in,
                              void* d_out, int out_size) {
    const float* pr = (const float*)d_in[0];
    const int ilast = (n_in > 1) ? (n_in - 1) : 0;
    const float* pi = (const float*)d_in[ilast];

    const long long n0 = (long long)in_sizes[0];
    const long long n1 = (long long)in_sizes[ilast];

    long long B = n0 / 4096;
    long long B_cap = (long long)out_size / ((long long)NT * NSC);
    if (B_cap < B) B = B_cap;
    if (B < 1) B = 1;
    if (B > BMAX) B = BMAX;

    const long long cap_f4 = (long long)out_size / 4;

    if (g_ok) {
        // fork both worker streams off the capture-origin (default) stream
        cudaEventRecord(g_evRoot, 0);
        cudaStreamWaitEvent(g_sA, g_evRoot, 0);
        cudaStreamWaitEvent(g_sB, g_evRoot, 0);

        const long long chunk = (B + NCHUNK - 1) / NCHUNK;
        for (int c = 0; c < NCHUNK; c++) {
            long long bs = (long long)c * chunk;
            if (bs >= B) break;
            long long bn = (bs + chunk <= B) ? chunk : (B - bs);
            fft_kernel<<<(int)(bn * 2), 128, 0, g_sA>>>(pr, pi, n0, n1, (int)(bs * 2));
            cudaEventRecord(g_evK1[c], g_sA);
            cudaStreamWaitEvent(g_sB, g_evK1[c], 0);
            out_kernel<<<(int)(bn * 4), 256, 0, g_sB>>>(pr, (float4*)d_out, n0, cap_f4,
                                                        (int)bs, (int)B);
        }
        // join back to origin stream (sB already depends on every sA chunk)
        cudaEventRecord(g_evJoin, g_sB);
        cudaStreamWaitEvent(0, g_evJoin, 0);
    } else {
        // fallback: serial on the default stream
        fft_kernel<<<(int)(B * 2), 128>>>(pr, pi, n0, n1, 0);
        out_kernel<<<(int)(B * 4), 256>>>(pr, (float4*)d_out, n0, cap_f4, 0, (int)B);
    }
}

// round 15
// speedup vs baseline: 5.1635x; 5.1635x over previous
#include <cuda_runtime.h>

#define NSC     4096
#define NT      14
#define THREADS 512
#define PAD(f)  ((f) + ((f) >> 3))
#define RSQ2    0.70710678118654752f
// shared (float2 units): Tb[0,256) | Y0[256,2560) | Y1[2560,4864) | R0[4864,5888) | R1[5888,6912)
#define SMEM_BYTES 55296

__constant__ float c_w[NT] = {0.f, 0.f, 0.f, 1.f/9, 2.f/9, 3.f/9, 4.f/9, 5.f/9,
                              6.f/9, 7.f/9, 8.f/9, 1.f, 1.f, 1.f};

__device__ __forceinline__ float2 cadd(float2 a, float2 b) { return make_float2(a.x + b.x, a.y + b.y); }
__device__ __forceinline__ float2 csub(float2 a, float2 b) { return make_float2(a.x - b.x, a.y - b.y); }
__device__ __forceinline__ float2 cmul(float2 a, float2 b) {
    return make_float2(a.x * b.x - a.y * b.y, a.x * b.y + a.y * b.x);
}

// Forward radix-8 DIF stage (L=8h). Twiddle index j*str <= 255.
__device__ __forceinline__ void fwd8(float2* __restrict__ A, const float2* __restrict__ Tb,
                                     int q, int h, int str) {
    int j    = q & (h - 1);
    int base = ((q - j) << 3) + j;
    float2 t0 = A[PAD(base)],         t1 = A[PAD(base + h)];
    float2 t2 = A[PAD(base + 2 * h)], t3 = A[PAD(base + 3 * h)];
    float2 t4 = A[PAD(base + 4 * h)], t5 = A[PAD(base + 5 * h)];
    float2 t6 = A[PAD(base + 6 * h)], t7 = A[PAD(base + 7 * h)];

    float2 a0 = cadd(t0, t4), a1 = cadd(t1, t5), a2 = cadd(t2, t6), a3 = cadd(t3, t7);
    float2 b0 = csub(t0, t4), b1 = csub(t1, t5), b2 = csub(t2, t6), b3 = csub(t3, t7);
    float2 c0 = cadd(a0, a2), c1 = csub(a0, a2), c2 = cadd(a1, a3), c3 = csub(a1, a3);
    float2 X0 = cadd(c0, c2), X4 = csub(c0, c2);
    float2 X2 = make_float2(c1.x + c3.y, c1.y - c3.x);
    float2 X6 = make_float2(c1.x - c3.y, c1.y + c3.x);
    float2 d0 = b0;
    float2 d1 = make_float2(RSQ2 * (b1.x + b1.y), RSQ2 * (b1.y - b1.x));
    float2 d2 = make_float2(b2.y, -b2.x);
    float2 d3 = make_float2(RSQ2 * (b3.y - b3.x), RSQ2 * (-(b3.x + b3.y)));
    float2 e0 = cadd(d0, d2), ee1 = csub(d0, d2), e2 = cadd(d1, d3), e3 = csub(d1, d3);
    float2 X1 = cadd(e0, e2), X5 = csub(e0, e2);
    float2 X3 = make_float2(ee1.x + e3.y, ee1.y - e3.x);
    float2 X7 = make_float2(ee1.x - e3.y, ee1.y + e3.x);

    float2 w1 = Tb[j * str]; w1.y = -w1.y;
    float2 w2 = cmul(w1, w1);
    float2 w3 = cmul(w2, w1);
    float2 w4 = cmul(w2, w2);
    float2 w5 = cmul(w4, w1);
    float2 w6 = cmul(w4, w2);
    float2 w7 = cmul(w4, w3);
    A[PAD(base)]         = X0;
    A[PAD(base + h)]     = cmul(X1, w1);
    A[PAD(base + 2 * h)] = cmul(X2, w2);
    A[PAD(base + 3 * h)] = cmul(X3, w3);
    A[PAD(base + 4 * h)] = cmul(X4, w4);
    A[PAD(base + 5 * h)] = cmul(X5, w5);
    A[PAD(base + 6 * h)] = cmul(X6, w6);
    A[PAD(base + 7 * h)] = cmul(X7, w7);
}

// Inverse radix-8 DIT stage. If LAST, write real parts only to R.
template <bool LAST>
__device__ __forceinline__ void inv8(float2* __restrict__ A, float* __restrict__ R,
                                     const float2* __restrict__ Tb,
                                     int q, int h, int str) {
    int j    = q & (h - 1);
    int base = ((q - j) << 3) + j;
    float2 w1 = Tb[j * str];
    float2 w2 = cmul(w1, w1);
    float2 w3 = cmul(w2, w1);
    float2 w4 = cmul(w2, w2);
    float2 w5 = cmul(w4, w1);
    float2 w6 = cmul(w4, w2);
    float2 w7 = cmul(w4, w3);
    float2 t0 = A[PAD(base)];
    float2 t1 = cmul(A[PAD(base + h)],     w1);
    float2 t2 = cmul(A[PAD(base + 2 * h)], w2);
    float2 t3 = cmul(A[PAD(base + 3 * h)], w3);
    float2 t4 = cmul(A[PAD(base + 4 * h)], w4);
    float2 t5 = cmul(A[PAD(base + 5 * h)], w5);
    float2 t6 = cmul(A[PAD(base + 6 * h)], w6);
    float2 t7 = cmul(A[PAD(base + 7 * h)], w7);

    float2 a0 = cadd(t0, t4), a1 = cadd(t1, t5), a2 = cadd(t2, t6), a3 = cadd(t3, t7);
    float2 b0 = csub(t0, t4), b1 = csub(t1, t5), b2 = csub(t2, t6), b3 = csub(t3, t7);
    float2 c0 = cadd(a0, a2), c1 = csub(a0, a2), c2 = cadd(a1, a3), c3 = csub(a1, a3);
    float2 X0 = cadd(c0, c2), X4 = csub(c0, c2);
    float2 X2 = make_float2(c1.x - c3.y, c1.y + c3.x);
    float2 X6 = make_float2(c1.x + c3.y, c1.y - c3.x);
    float2 d0 = b0;
    float2 d1 = make_float2(RSQ2 * (b1.x - b1.y), RSQ2 * (b1.y + b1.x));
    float2 d2 = make_float2(-b2.y, b2.x);
    float2 d3 = make_float2(RSQ2 * (-(b3.x + b3.y)), RSQ2 * (b3.x - b3.y));
    float2 e0 = cadd(d0, d2), ee1 = csub(d0, d2), e2 = cadd(d1, d3), e3 = csub(d1, d3);
    float2 X1 = cadd(e0, e2), X5 = csub(e0, e2);
    float2 X3 = make_float2(ee1.x - e3.y, ee1.y + e3.x);
    float2 X7 = make_float2(ee1.x + e3.y, ee1.y - e3.x);

    if (LAST) {
        R[base]         = X0.x;
        R[base + h]     = X1.x;
        R[base + 2 * h] = X2.x;
        R[base + 3 * h] = X3.x;
        R[base + 4 * h] = X4.x;
        R[base + 5 * h] = X5.x;
        R[base + 6 * h] = X6.x;
        R[base + 7 * h] = X7.x;
    } else {
        A[PAD(base)]         = X0;
        A[PAD(base + h)]     = X1;
        A[PAD(base + 2 * h)] = X2;
        A[PAD(base + 3 * h)] = X3;
        A[PAD(base + 4 * h)] = X4;
        A[PAD(base + 5 * h)] = X5;
        A[PAD(base + 6 * h)] = X6;
        A[PAD(base + 7 * h)] = X7;
    }
}

// fused middle: forward radix-2... (radix-4 L=4) + pointwise w/2048 + inverse radix-4
__device__ __forceinline__ void mid_stage(float2* __restrict__ Y0, float2* __restrict__ Y1, int tid) {
    int m = tid;                                        // quad index [0,512)
    int revm = ((m & 7) << 6) | (m & 56) | (m >> 6);    // 3-octal-digit reverse
    float sn, cs;
    __sincosf((float)revm * 1.5339807878856412e-3f, &sn, &cs);   // 2*pi/4096
    float2 w0 = make_float2(cs * (1.0f / 2048.0f), sn * (1.0f / 2048.0f));
    float2 wA = make_float2(RSQ2 * (w0.x - w0.y), RSQ2 * (w0.x + w0.y));
    float2 wB = make_float2(w0.y, -w0.x);
    float2 wC = make_float2(RSQ2 * (w0.x + w0.y), RSQ2 * (w0.y - w0.x));
    int p = 4 * m;
    #pragma unroll
    for (int s = 0; s < 2; s++) {
        float2* A = s ? Y1 : Y0;
        float2 t0 = A[PAD(p)],     t1 = A[PAD(p + 1)];
        float2 t2 = A[PAD(p + 2)], t3 = A[PAD(p + 3)];
        float2 a = cadd(t0, t2), bb = csub(t0, t2);
        float2 c = cadd(t1, t3), d  = csub(t1, t3);
        float2 F0 = cadd(a, c);
        float2 F1 = make_float2(bb.x + d.y, bb.y - d.x);
        float2 F2 = csub(a, c);
        float2 F3 = make_float2(bb.x - d.y, bb.y + d.x);
        float2 G0 = cmul(F0, w0), G1 = cmul(F1, wA);
        float2 G2 = cmul(F2, wB), G3 = cmul(F3, wC);
        float2 ap = cadd(G0, G2), bp = csub(G0, G2);
        float2 cp = cadd(G1, G3), dp = csub(G1, G3);
        A[PAD(p)]     = cadd(ap, cp);
        A[PAD(p + 2)] = csub(ap, cp);
        A[PAD(p + 1)] = make_float2(bp.x - dp.y, bp.y + dp.x);
        A[PAD(p + 3)] = make_float2(bp.x + dp.y, bp.y - dp.x);
    }
}

// store nt consecutive t-slices of batch b's output (both quads owned by tid)
__device__ __forceinline__ void store_slice(const float* __restrict__ pr,
                                            const float* __restrict__ R0,
                                            const float* __restrict__ R1,
                                            float4* __restrict__ out,
                                            long long n0, long long cap_f4,
                                            int b, int tid, int t0, int nt) {
    const long long base = (long long)b * 4096;
    const long long obf4 = (long long)b * (NT * NSC / 4);
    const bool ok = (obf4 + (long long)NT * (NSC / 4) <= cap_f4) && (base + 4096 <= n0);
    const float2* pr2 = (const float2*)pr;
    const float2* R0v = (const float2*)R0;
    const float2* R1v = (const float2*)R1;
    #pragma unroll
    for (int wq = 0; wq < 2; wq++) {
        int u = tid + wq * THREADS;                 // quad index [0,1024)
        float2 e0, e1;
        if (ok) {
            e0 = pr2[(base >> 1) + u];
            e1 = pr2[(base >> 1) + 1024 + u];
        } else {
            e0.x = (base + 2 * u < n0) ? pr[base + 2 * u] : 0.0f;
            e0.y = (base + 2 * u + 1 < n0) ? pr[base + 2 * u + 1] : 0.0f;
            e1.x = (base + 2048 + 2 * u < n0) ? pr[base + 2048 + 2 * u] : 0.0f;
            e1.y = (base + 2048 + 2 * u + 1 < n0) ? pr[base + 2048 + 2 * u + 1] : 0.0f;
        }
        float2 o0 = R0v[u];
        float2 o1 = R1v[u];
        for (int dt = 0; dt < nt; dt++) {
            int t = t0 + dt;
            float w = c_w[t];
            float4 v;
            v.x = e0.x + (e1.x - e0.x) * w;
            v.y = o0.x + (o1.x - o0.x) * w;
            v.z = e0.y + (e1.y - e0.y) * w;
            v.w = o0.y + (o1.y - o0.y) * w;
            long long f4 = obf4 + (long long)t * (NSC / 4) + u;
            if (ok)               out[f4] = v;
            else if (f4 < cap_f4) out[f4] = v;
        }
    }
}

__device__ __forceinline__ void load_batch(const float* __restrict__ pr,
                                           const float* __restrict__ pi,
                                           float2* __restrict__ Y0, float2* __restrict__ Y1,
                                           long long n0, long long n1, int b, int tid) {
    const long long base = (long long)b * 4096;
    for (int n = tid; n < 2048; n += THREADS) {
        long long i0 = base + n;
        long long i1 = base + n + 2048;
        float r0 = (i0 < n0) ? pr[i0] : 0.0f;
        float m0 = (i0 < n1) ? pi[i0] : 0.0f;
        float r1 = (i1 < n0) ? pr[i1] : 0.0f;
        float m1 = (i1 < n1) ? pi[i1] : 0.0f;
        Y0[PAD(n)] = make_float2(r0, m0);
        Y1[PAD(n)] = make_float2(r1, m1);
    }
}

__global__ __launch_bounds__(THREADS, 2) void tdi_kernel(const float* __restrict__ pr,
                                                         const float* __restrict__ pi,
                                                         float4* __restrict__ out,
                                                         long long n0, long long n1,
                                                         long long cap_f4, int B)
{
    extern __shared__ float2 sh[];
    float2* Tb = sh;                    // 256 entries
    float2* Y0 = sh + 256;
    float2* Y1 = sh + 2560;
    float*  R0 = (float*)(sh + 4864);   // 2048 floats
    float*  R1 = R0 + 2048;             // 2048 floats

    const int tid = threadIdx.x;
    const int q   = tid & 255;
    const int sel = tid >> 8;
    const int bA  = 2 * blockIdx.x;
    int bB        = 2 * blockIdx.x + 1;
    if (bB >= B) bB = bA;               // odd-B edge: redo bA (same data, benign)

    if (tid < 256) {
        float s, c;
        __sincosf((float)tid * 3.0679615757712823e-3f, &s, &c);   // 2*pi/2048
        Tb[tid] = make_float2(c, s);
    }
    load_batch(pr, pi, Y0, Y1, n0, n1, bA, tid);
    __syncthreads();

    float2* Yq = sel ? Y1 : Y0;
    float*  Rq = sel ? R1 : R0;

    // ---- FFT batch A ----
    fwd8(Yq, Tb, q, 256, 1);  __syncthreads();
    fwd8(Yq, Tb, q, 32,  8);  __syncthreads();
    fwd8(Yq, Tb, q, 4,   64); __syncthreads();
    mid_stage(Y0, Y1, tid);   __syncthreads();
    inv8<false>(Yq, (float*)0, Tb, q, 4,  64); __syncthreads();
    inv8<false>(Yq, (float*)0, Tb, q, 32, 8);  __syncthreads();
    inv8<true> (Yq, Rq, Tb, q, 256, 1);        __syncthreads();

    // ---- load batch B (Y is free), keep R = batch A results ----
    load_batch(pr, pi, Y0, Y1, n0, n1, bB, tid);
    __syncthreads();

    // ---- FFT batch B with batch-A stores interleaved in the stage gaps ----
    store_slice(pr, R0, R1, out, n0, cap_f4, bA, tid, 0, 2);
    fwd8(Yq, Tb, q, 256, 1);  __syncthreads();
    store_slice(pr, R0, R1, out, n0, cap_f4, bA, tid, 2, 2);
    fwd8(Yq, Tb, q, 32,  8);  __syncthreads();
    store_slice(pr, R0, R1, out, n0, cap_f4, bA, tid, 4, 2);
    fwd8(Yq, Tb, q, 4,   64); __syncthreads();
    store_slice(pr, R0, R1, out, n0, cap_f4, bA, tid, 6, 2);
    mid_stage(Y0, Y1, tid);   __syncthreads();
    store_slice(pr, R0, R1, out, n0, cap_f4, bA, tid, 8, 2);
    inv8<false>(Yq, (float*)0, Tb, q, 4,  64); __syncthreads();
    store_slice(pr, R0, R1, out, n0, cap_f4, bA, tid, 10, 2);
    inv8<false>(Yq, (float*)0, Tb, q, 32, 8);  __syncthreads();
    store_slice(pr, R0, R1, out, n0, cap_f4, bA, tid, 12, 2);
    __syncthreads();                            // all A-stores done before R is overwritten
    inv8<true> (Yq, Rq, Tb, q, 256, 1);        __syncthreads();

    // ---- tail: store batch B (skip if duplicate of A on odd-B edge) ----
    if (bB != bA || (B & 1) == 0 || blockIdx.x * 2 == B - 1)
        store_slice(pr, R0, R1, out, n0, cap_f4, bB, tid, 0, NT);
}

extern "C" void kernel_launch(void* const* d_in, const int* in_sizes, int n_in,
                              void* d_out, int out_size) {
    const float* pr = (const float*)d_in[0];
    const int ilast = (n_in > 1) ? (n_in - 1) : 0;
    const float* pi = (const float*)d_in[ilast];

    const long long n0 = (long long)in_sizes[0];
    const long long n1 = (long long)in_sizes[ilast];

    long long B = n0 / 4096;
    long long B_cap = (long long)out_size / ((long long)NT * NSC);
    if (B_cap < B) B = B_cap;
    if (B < 1) B = 1;
    if (B > 65535) B = 65535;

    const long long cap_f4 = (long long)out_size / 4;
    const int grid = (int)((B + 1) / 2);

    static bool attr_done = false;
    if (!attr_done) {
        cudaFuncSetAttribute(tdi_kernel, cudaFuncAttributeMaxDynamicSharedMemorySize, SMEM_BYTES);
        attr_done = true;
    }
    tdi_kernel<<<grid, THREADS, SMEM_BYTES>>>(pr, pi, (float4*)d_out, n0, n1, cap_f4, (int)B);
}

// round 16
// speedup vs baseline: 5.4629x; 1.0580x over previous
#include <cuda_runtime.h>

#define NSC     4096
#define NT      14
#define THREADS 512
#define PAD(f)  ((f) + ((f) >> 3))
#define RSQ2    0.70710678118654752f
// shared (float2 units): Tb[0,256) | Y0[256,2560) | Y1[2560,4864) | R0[4864,5888) | R1[5888,6912)
#define SMEM_BYTES 55296

__constant__ float c_w[NT] = {0.f, 0.f, 0.f, 1.f/9, 2.f/9, 3.f/9, 4.f/9, 5.f/9,
                              6.f/9, 7.f/9, 8.f/9, 1.f, 1.f, 1.f};

__device__ __forceinline__ void hsync(int sel) {
    // per-half named barrier: ids 1 and 2 (0 reserved for __syncthreads)
    asm volatile("bar.sync %0, 256;" :: "r"(sel + 1) : "memory");
}

__device__ __forceinline__ float2 cadd(float2 a, float2 b) { return make_float2(a.x + b.x, a.y + b.y); }
__device__ __forceinline__ float2 csub(float2 a, float2 b) { return make_float2(a.x - b.x, a.y - b.y); }
__device__ __forceinline__ float2 cmul(float2 a, float2 b) {
    return make_float2(a.x * b.x - a.y * b.y, a.x * b.y + a.y * b.x);
}

// Forward radix-8 DIF stage (L=8h). Twiddle index j*str <= 255.
__device__ __forceinline__ void fwd8(float2* __restrict__ A, const float2* __restrict__ Tb,
                                     int q, int h, int str) {
    int j    = q & (h - 1);
    int base = ((q - j) << 3) + j;
    float2 t0 = A[PAD(base)],         t1 = A[PAD(base + h)];
    float2 t2 = A[PAD(base + 2 * h)], t3 = A[PAD(base + 3 * h)];
    float2 t4 = A[PAD(base + 4 * h)], t5 = A[PAD(base + 5 * h)];
    float2 t6 = A[PAD(base + 6 * h)], t7 = A[PAD(base + 7 * h)];

    float2 a0 = cadd(t0, t4), a1 = cadd(t1, t5), a2 = cadd(t2, t6), a3 = cadd(t3, t7);
    float2 b0 = csub(t0, t4), b1 = csub(t1, t5), b2 = csub(t2, t6), b3 = csub(t3, t7);
    float2 c0 = cadd(a0, a2), c1 = csub(a0, a2), c2 = cadd(a1, a3), c3 = csub(a1, a3);
    float2 X0 = cadd(c0, c2), X4 = csub(c0, c2);
    float2 X2 = make_float2(c1.x + c3.y, c1.y - c3.x);
    float2 X6 = make_float2(c1.x - c3.y, c1.y + c3.x);
    float2 d0 = b0;
    float2 d1 = make_float2(RSQ2 * (b1.x + b1.y), RSQ2 * (b1.y - b1.x));
    float2 d2 = make_float2(b2.y, -b2.x);
    float2 d3 = make_float2(RSQ2 * (b3.y - b3.x), RSQ2 * (-(b3.x + b3.y)));
    float2 e0 = cadd(d0, d2), ee1 = csub(d0, d2), e2 = cadd(d1, d3), e3 = csub(d1, d3);
    float2 X1 = cadd(e0, e2), X5 = csub(e0, e2);
    float2 X3 = make_float2(ee1.x + e3.y, ee1.y - e3.x);
    float2 X7 = make_float2(ee1.x - e3.y, ee1.y + e3.x);

    float2 w1 = Tb[j * str]; w1.y = -w1.y;
    float2 w2 = cmul(w1, w1);
    float2 w3 = cmul(w2, w1);
    float2 w4 = cmul(w2, w2);
    float2 w5 = cmul(w4, w1);
    float2 w6 = cmul(w4, w2);
    float2 w7 = cmul(w4, w3);
    A[PAD(base)]         = X0;
    A[PAD(base + h)]     = cmul(X1, w1);
    A[PAD(base + 2 * h)] = cmul(X2, w2);
    A[PAD(base + 3 * h)] = cmul(X3, w3);
    A[PAD(base + 4 * h)] = cmul(X4, w4);
    A[PAD(base + 5 * h)] = cmul(X5, w5);
    A[PAD(base + 6 * h)] = cmul(X6, w6);
    A[PAD(base + 7 * h)] = cmul(X7, w7);
}

// Inverse radix-8 DIT stage. If LAST, write real parts only to R.
template <bool LAST>
__device__ __forceinline__ void inv8(float2* __restrict__ A, float* __restrict__ R,
                                     const float2* __restrict__ Tb,
                                     int q, int h, int str) {
    int j    = q & (h - 1);
    int base = ((q - j) << 3) + j;
    float2 w1 = Tb[j * str];
    float2 w2 = cmul(w1, w1);
    float2 w3 = cmul(w2, w1);
    float2 w4 = cmul(w2, w2);
    float2 w5 = cmul(w4, w1);
    float2 w6 = cmul(w4, w2);
    float2 w7 = cmul(w4, w3);
    float2 t0 = A[PAD(base)];
    float2 t1 = cmul(A[PAD(base + h)],     w1);
    float2 t2 = cmul(A[PAD(base + 2 * h)], w2);
    float2 t3 = cmul(A[PAD(base + 3 * h)], w3);
    float2 t4 = cmul(A[PAD(base + 4 * h)], w4);
    float2 t5 = cmul(A[PAD(base + 5 * h)], w5);
    float2 t6 = cmul(A[PAD(base + 6 * h)], w6);
    float2 t7 = cmul(A[PAD(base + 7 * h)], w7);

    float2 a0 = cadd(t0, t4), a1 = cadd(t1, t5), a2 = cadd(t2, t6), a3 = cadd(t3, t7);
    float2 b0 = csub(t0, t4), b1 = csub(t1, t5), b2 = csub(t2, t6), b3 = csub(t3, t7);
    float2 c0 = cadd(a0, a2), c1 = csub(a0, a2), c2 = cadd(a1, a3), c3 = csub(a1, a3);
    float2 X0 = cadd(c0, c2), X4 = csub(c0, c2);
    float2 X2 = make_float2(c1.x - c3.y, c1.y + c3.x);
    float2 X6 = make_float2(c1.x + c3.y, c1.y - c3.x);
    float2 d0 = b0;
    float2 d1 = make_float2(RSQ2 * (b1.x - b1.y), RSQ2 * (b1.y + b1.x));
    float2 d2 = make_float2(-b2.y, b2.x);
    float2 d3 = make_float2(RSQ2 * (-(b3.x + b3.y)), RSQ2 * (b3.x - b3.y));
    float2 e0 = cadd(d0, d2), ee1 = csub(d0, d2), e2 = cadd(d1, d3), e3 = csub(d1, d3);
    float2 X1 = cadd(e0, e2), X5 = csub(e0, e2);
    float2 X3 = make_float2(ee1.x - e3.y, ee1.y + e3.x);
    float2 X7 = make_float2(ee1.x + e3.y, ee1.y - e3.x);

    if (LAST) {
        R[base]         = X0.x;
        R[base + h]     = X1.x;
        R[base + 2 * h] = X2.x;
        R[base + 3 * h] = X3.x;
        R[base + 4 * h] = X4.x;
        R[base + 5 * h] = X5.x;
        R[base + 6 * h] = X6.x;
        R[base + 7 * h] = X7.x;
    } else {
        A[PAD(base)]         = X0;
        A[PAD(base + h)]     = X1;
        A[PAD(base + 2 * h)] = X2;
        A[PAD(base + 3 * h)] = X3;
        A[PAD(base + 4 * h)] = X4;
        A[PAD(base + 5 * h)] = X5;
        A[PAD(base + 6 * h)] = X6;
        A[PAD(base + 7 * h)] = X7;
    }
}

// fused middle on ONE array: quads m = q and q+256
__device__ __forceinline__ void mid_half(float2* __restrict__ A, int q) {
    #pragma unroll
    for (int it = 0; it < 2; it++) {
        int m = q + it * 256;                               // quad index [0,512)
        int revm = ((m & 7) << 6) | (m & 56) | (m >> 6);    // 3-octal-digit reverse
        float sn, cs;
        __sincosf((float)revm * 1.5339807878856412e-3f, &sn, &cs);   // 2*pi/4096
        float2 w0 = make_float2(cs * (1.0f / 2048.0f), sn * (1.0f / 2048.0f));
        float2 wA = make_float2(RSQ2 * (w0.x - w0.y), RSQ2 * (w0.x + w0.y));
        float2 wB = make_float2(w0.y, -w0.x);
        float2 wC = make_float2(RSQ2 * (w0.x + w0.y), RSQ2 * (w0.y - w0.x));
        int p = 4 * m;
        float2 t0 = A[PAD(p)],     t1 = A[PAD(p + 1)];
        float2 t2 = A[PAD(p + 2)], t3 = A[PAD(p + 3)];
        float2 a = cadd(t0, t2), bb = csub(t0, t2);
        float2 c = cadd(t1, t3), d  = csub(t1, t3);
        float2 F0 = cadd(a, c);
        float2 F1 = make_float2(bb.x + d.y, bb.y - d.x);
        float2 F2 = csub(a, c);
        float2 F3 = make_float2(bb.x - d.y, bb.y + d.x);
        float2 G0 = cmul(F0, w0), G1 = cmul(F1, wA);
        float2 G2 = cmul(F2, wB), G3 = cmul(F3, wC);
        float2 ap = cadd(G0, G2), bp = csub(G0, G2);
        float2 cp = cadd(G1, G3), dp = csub(G1, G3);
        A[PAD(p)]     = cadd(ap, cp);
        A[PAD(p + 2)] = csub(ap, cp);
        A[PAD(p + 1)] = make_float2(bp.x - dp.y, bp.y + dp.x);
        A[PAD(p + 3)] = make_float2(bp.x + dp.y, bp.y - dp.x);
    }
}

// store nt consecutive t-slices of batch b's output (both quads owned by tid)
__device__ __forceinline__ void store_slice(const float* __restrict__ pr,
                                            const float* __restrict__ R0,
                                            const float* __restrict__ R1,
                                            float4* __restrict__ out,
                                            long long n0, long long cap_f4,
                                            int b, int tid, int t0, int nt) {
    const long long base = (long long)b * 4096;
    const long long obf4 = (long long)b * (NT * NSC / 4);
    const bool ok = (obf4 + (long long)NT * (NSC / 4) <= cap_f4) && (base + 4096 <= n0);
    const float2* pr2 = (const float2*)pr;
    const float2* R0v = (const float2*)R0;
    const float2* R1v = (const float2*)R1;
    #pragma unroll
    for (int wq = 0; wq < 2; wq++) {
        int u = tid + wq * THREADS;                 // quad index [0,1024)
        float2 e0, e1;
        if (ok) {
            e0 = pr2[(base >> 1) + u];
            e1 = pr2[(base >> 1) + 1024 + u];
        } else {
            e0.x = (base + 2 * u < n0) ? pr[base + 2 * u] : 0.0f;
            e0.y = (base + 2 * u + 1 < n0) ? pr[base + 2 * u + 1] : 0.0f;
            e1.x = (base + 2048 + 2 * u < n0) ? pr[base + 2048 + 2 * u] : 0.0f;
            e1.y = (base + 2048 + 2 * u + 1 < n0) ? pr[base + 2048 + 2 * u + 1] : 0.0f;
        }
        float2 o0 = R0v[u];
        float2 o1 = R1v[u];
        for (int dt = 0; dt < nt; dt++) {
            int t = t0 + dt;
            float w = c_w[t];
            float4 v;
            v.x = e0.x + (e1.x - e0.x) * w;
            v.y = o0.x + (o1.x - o0.x) * w;
            v.z = e0.y + (e1.y - e0.y) * w;
            v.w = o0.y + (o1.y - o0.y) * w;
            long long f4 = obf4 + (long long)t * (NSC / 4) + u;
            if (ok)               out[f4] = v;
            else if (f4 < cap_f4) out[f4] = v;
        }
    }
}

// half-local load: this half's threads load their own symbol array
__device__ __forceinline__ void load_half(const float* __restrict__ pr,
                                          const float* __restrict__ pi,
                                          float2* __restrict__ Yq,
                                          long long n0, long long n1,
                                          int b, int q, int sel) {
    const long long base = (long long)b * 4096 + (long long)sel * 2048;
    #pragma unroll
    for (int i = 0; i < 8; i++) {
        int n = q + i * 256;
        long long idx = base + n;
        float r = (idx < n0) ? pr[idx] : 0.0f;
        float m = (idx < n1) ? pi[idx] : 0.0f;
        Yq[PAD(n)] = make_float2(r, m);
    }
}

__global__ __launch_bounds__(THREADS, 2) void tdi_kernel(const float* __restrict__ pr,
                                                         const float* __restrict__ pi,
                                                         float4* __restrict__ out,
                                                         long long n0, long long n1,
                                                         long long cap_f4, int B)
{
    extern __shared__ float2 sh[];
    float2* Tb = sh;                    // 256 entries
    float2* Y0 = sh + 256;
    float2* Y1 = sh + 2560;
    float*  R0 = (float*)(sh + 4864);   // 2048 floats
    float*  R1 = R0 + 2048;             // 2048 floats

    const int tid = threadIdx.x;
    const int q   = tid & 255;
    const int sel = tid >> 8;
    const int bA  = 2 * blockIdx.x;
    int bB        = 2 * blockIdx.x + 1;
    if (bB >= B) bB = bA;               // odd-B edge: redo bA (benign duplicate)

    if (tid < 256) {
        float s, c;
        __sincosf((float)tid * 3.0679615757712823e-3f, &s, &c);   // 2*pi/2048
        Tb[tid] = make_float2(c, s);
    }
    float2* Yq = sel ? Y1 : Y0;
    float*  Rq = sel ? R1 : R0;
    load_half(pr, pi, Yq, n0, n1, bA, q, sel);
    __syncthreads();                    // Tb + both Y halves visible

    // ---- FFT batch A (per-half barriers; halves decoupled) ----
    fwd8(Yq, Tb, q, 256, 1);  hsync(sel);
    fwd8(Yq, Tb, q, 32,  8);  hsync(sel);
    fwd8(Yq, Tb, q, 4,   64); hsync(sel);
    mid_half(Yq, q);          hsync(sel);
    inv8<false>(Yq, (float*)0, Tb, q, 4,  64); hsync(sel);
    inv8<false>(Yq, (float*)0, Tb, q, 32, 8);  hsync(sel);
    inv8<true> (Yq, Rq, Tb, q, 256, 1);
    __syncthreads();                    // R0+R1 complete, visible to all

    // ---- load batch B (half-local; own Y is free) ----
    load_half(pr, pi, Yq, n0, n1, bB, q, sel);
    hsync(sel);

    // ---- FFT batch B with batch-A stores interleaved in the stage gaps ----
    store_slice(pr, R0, R1, out, n0, cap_f4, bA, tid, 0, 2);
    fwd8(Yq, Tb, q, 256, 1);  hsync(sel);
    store_slice(pr, R0, R1, out, n0, cap_f4, bA, tid, 2, 2);
    fwd8(Yq, Tb, q, 32,  8);  hsync(sel);
    store_slice(pr, R0, R1, out, n0, cap_f4, bA, tid, 4, 2);
    fwd8(Yq, Tb, q, 4,   64); hsync(sel);
    store_slice(pr, R0, R1, out, n0, cap_f4, bA, tid, 6, 2);
    mid_half(Yq, q);          hsync(sel);
    store_slice(pr, R0, R1, out, n0, cap_f4, bA, tid, 8, 2);
    inv8<false>(Yq, (float*)0, Tb, q, 4,  64); hsync(sel);
    store_slice(pr, R0, R1, out, n0, cap_f4, bA, tid, 10, 2);
    inv8<false>(Yq, (float*)0, Tb, q, 32, 8);  hsync(sel);
    store_slice(pr, R0, R1, out, n0, cap_f4, bA, tid, 12, 2);
    __syncthreads();                    // all A-stores done before R overwritten
    inv8<true> (Yq, Rq, Tb, q, 256, 1);
    __syncthreads();                    // R(B) complete both halves

    // ---- tail: store batch B (duplicate on odd-B edge is benign) ----
    store_slice(pr, R0, R1, out, n0, cap_f4, bB, tid, 0, NT);
}

extern "C" void kernel_launch(void* const* d_in, const int* in_sizes, int n_in,
                              void* d_out, int out_size) {
    const float* pr = (const float*)d_in[0];
    const int ilast = (n_in > 1) ? (n_in - 1) : 0;
    const float* pi = (const float*)d_in[ilast];

    const long long n0 = (long long)in_sizes[0];
    const long long n1 = (long long)in_sizes[ilast];

    long long B = n0 / 4096;
    long long B_cap = (long long)out_size / ((long long)NT * NSC);
    if (B_cap < B) B = B_cap;
    if (B < 1) B = 1;
    if (B > 65535) B = 65535;

    const long long cap_f4 = (long long)out_size / 4;
    const int grid = (int)((B + 1) / 2);

    static bool attr_done = false;
    if (!attr_done) {
        cudaFuncSetAttribute(tdi_kernel, cudaFuncAttributeMaxDynamicSharedMemorySize, SMEM_BYTES);
        attr_done = true;
    }
    tdi_kernel<<<grid, THREADS, SMEM_BYTES>>>(pr, pi, (float4*)d_out, n0, n1, cap_f4, (int)B);
}